// round 7
// baseline (speedup 1.0000x reference)
#include <cuda_runtime.h>
#include <math.h>

typedef unsigned long long ull;

// Problem constants
#define DHID   1024
#define BATCH  32
#define TSTEPS 513           // GRU steps (U+1)
#define N3     3072
#define NCTA   128           // persistent grid: 8 hidden units per CTA, 1 CTA/SM

// SMEM: Wh slice [24 rows][1024] (96KB) + exchange [16 warps][24 rows][32 b] (48KB)
#define WH_SM_FLOATS (24 * 1024)
#define EXCH_FLOATS  (16 * 24 * 32)
#define STEP_SMEM    ((WH_SM_FLOATS + EXCH_FLOATS) * 4)   // 147456 bytes

// ---------------- f32x2 packed-FMA helpers ----------------
#define FMA2(acc, a, b) asm("fma.rn.f32x2 %0, %1, %2, %0;" : "+l"(acc) : "l"(a), "l"(b))
#define PACKDUP(d, v)   asm("mov.b64 %0, {%1, %1};" : "=l"(d) : "f"(v))
#define UNPK(lo, hi, v) asm("mov.b64 {%0, %1}, %2;" : "=f"(lo), "=f"(hi) : "l"(v))

// ---------------- device scratch (no allocation allowed) ----------------
__device__ float g_Eproj[1024 * N3];                       // embed @ Wx + bx (12.6 MB)
__device__ uint4 g_WhT4[(size_t)N3 * (DHID / 4)];          // Wh^T [3D][D], 16B aligned
__device__ uint4 g_hp4[(size_t)(TSTEPS + 1) * (BATCH * DHID / 4)];  // h packed [s][k4][b][4]
__device__ float g_hf[(size_t)(TSTEPS + 1) * BATCH * DHID];         // h flat   [s][b][k]
__device__ unsigned g_cnt[TSTEPS + 2];                     // per-step barrier counters

// ---------------- init: packed h0 broadcast + barrier counter reset ----------------
__global__ void init_kernel(const float* __restrict__ h0) {
    int idx = blockIdx.x * blockDim.x + threadIdx.x;       // 32768 threads
    int k = ((idx >> 7) << 2) | (idx & 3);                 // packed [k4][b][4]
    ((float*)g_hp4)[idx] = h0[k];
    if (idx < TSTEPS + 2) g_cnt[idx] = 0;
}

// ---------------- transpose Wh [D,3D] -> WhT [3D,D] ----------------
__global__ void transpose_wh_kernel(const float* __restrict__ Wh) {
    __shared__ float t[32][33];
    int j = blockIdx.x * 32 + threadIdx.x;
    int d = blockIdx.y * 32 + threadIdx.y;
    t[threadIdx.y][threadIdx.x] = Wh[(size_t)d * N3 + j];
    __syncthreads();
    int dd = blockIdx.y * 32 + threadIdx.x;
    int jj = blockIdx.x * 32 + threadIdx.y;
    ((float*)g_WhT4)[(size_t)jj * DHID + dd] = t[threadIdx.x][threadIdx.y];
}

// ---------------- packed-fp32 tiled GEMM: C = A[M,K]*B[K,N] + bias ----------------
// mode 0: C[row*N+col]   mode 1: row=t*32+b -> C[(b*513+t)*1024+col]
__global__ __launch_bounds__(256)
void gemm_bias_kernel(const float* __restrict__ A, const float* __restrict__ Bm,
                      const float* __restrict__ bias, float* __restrict__ C,
                      int M, int N, int K, int mode) {
    __shared__ ull   sAd[32][65];
    __shared__ float sB[32][64];
    int bm = blockIdx.y * 64, bn = blockIdx.x * 64;
    int tid = threadIdx.x;
    int tr = tid >> 4, tc = tid & 15;
    ull acc[4][2];
#pragma unroll
    for (int i = 0; i < 4; i++) { acc[i][0] = 0ull; acc[i][1] = 0ull; }

    for (int k0 = 0; k0 < K; k0 += 32) {
#pragma unroll
        for (int i = tid; i < 64 * 32; i += 256) {
            int r = i >> 5, cc = i & 31;
            int gr = bm + r;
            float v = (gr < M) ? A[(size_t)gr * K + k0 + cc] : 0.f;
            ull dv; PACKDUP(dv, v);
            sAd[cc][r] = dv;
        }
#pragma unroll
        for (int i = tid; i < 32 * 64; i += 256) {
            int r = i >> 6, cc = i & 63;
            sB[r][cc] = Bm[(size_t)(k0 + r) * N + bn + cc];
        }
        __syncthreads();
#pragma unroll
        for (int kk = 0; kk < 32; kk++) {
            ull a0 = sAd[kk][tr * 4 + 0];
            ull a1 = sAd[kk][tr * 4 + 1];
            ull a2 = sAd[kk][tr * 4 + 2];
            ull a3 = sAd[kk][tr * 4 + 3];
            ull b0 = *(const ull*)&sB[kk][tc * 4];
            ull b1 = *(const ull*)&sB[kk][tc * 4 + 2];
            FMA2(acc[0][0], a0, b0); FMA2(acc[0][1], a0, b1);
            FMA2(acc[1][0], a1, b0); FMA2(acc[1][1], a1, b1);
            FMA2(acc[2][0], a2, b0); FMA2(acc[2][1], a2, b1);
            FMA2(acc[3][0], a3, b0); FMA2(acc[3][1], a3, b1);
        }
        __syncthreads();
    }
#pragma unroll
    for (int i = 0; i < 4; i++) {
        int row = bm + tr * 4 + i;
        if (row >= M) continue;
#pragma unroll
        for (int j2 = 0; j2 < 2; j2++) {
            float lo, hi; UNPK(lo, hi, acc[i][j2]);
            int c0 = bn + tc * 4 + 2 * j2;
            float v0 = lo + bias[c0];
            float v1 = hi + bias[c0 + 1];
            if (mode == 0) {
                C[(size_t)row * N + c0]     = v0;
                C[(size_t)row * N + c0 + 1] = v1;
            } else {
                int t = row >> 5, b = row & 31;
                size_t o = ((size_t)b * 513 + t) * 1024 + c0;
                C[o]     = v0;
                C[o + 1] = v1;
            }
        }
    }
}

// ---------------- persistent GRU recurrence ----------------
// 128 CTAs x 512 threads (1/SM, 4 warps/SMSP for latency hiding).
// CTA owns units j = bid*8..bid*8+7 (24 Wh rows in SMEM for the whole launch).
// Warp w reduces k-slice [w*64, w*64+64) for ALL 24 rows x 32 batches
// (lane = batch): per k4 -> 1 LDG.128 of h (.cg, L2) + 24 uniform 16B LDS of
// Wh + 48 FFMA2. 16 partials exchanged via SMEM; threads 0..255 run the gate
// epilogue (thread = (unit,batch)); fence-free release/acquire grid barrier.
__global__ __launch_bounds__(512, 1)
void gru_persist_kernel(const float* __restrict__ bh, const int* __restrict__ y) {
    extern __shared__ float sm[];
    float* swh = sm;                       // [24][1024]
    float* sex = sm + WH_SM_FLOATS;        // [16 warps][24 rows][32 b]

    const int tid  = threadIdx.x;
    const int lane = tid & 31;
    const int w    = tid >> 5;             // 0..15
    const int jbase = blockIdx.x * 8;

    // one-time: load Wh slice into SMEM (row r = u*3+g <- WhT row g*1024+jbase+u)
    for (int i = tid; i < 24 * 256; i += 512) {
        int r = i >> 8, c = i & 255;
        int u = r / 3, g = r - 3 * u;
        ((uint4*)swh)[r * 256 + c] = g_WhT4[(size_t)(g * 1024 + jbase + u) * 256 + c];
    }

    // epilogue constants: thread (unit u=w, batch b=lane), threads 0..255 only
    const bool epi = (tid < 256);
    const int j = epi ? (jbase + w) : jbase;
    float bz = 0.f, br = 0.f, bq = 0.f;
    int holdoff = 0;
    if (epi) {
        bz = bh[j]; br = bh[DHID + j]; bq = bh[2 * DHID + j];
        holdoff = ((j >> 2) * 32 + lane) * 4 + (j & 3);    // packed idx of h[b][j]
    }
    __syncthreads();

    const float* wb0 = swh + (w * 16) * 4;   // warp's k4 base (w*16 .. w*16+15)

    for (int s = 1; s <= TSTEPS; ++s) {
        const size_t sbase = (size_t)(s - 1) * 8192;

        // prefetch epilogue inputs early (hidden under the FMA loop)
        float ez = 0.f, er = 0.f, eq = 0.f, hold = 0.f;
        if (epi) {
            int tok = (s == 1) ? 0 : __ldg(&y[lane * 512 + (s - 2)]);
            const float* ep = g_Eproj + (size_t)tok * N3;
            ez = __ldg(ep + j);
            er = __ldg(ep + DHID + j);
            eq = __ldg(ep + 2 * DHID + j);
            hold = __ldcg(((const float*)g_hp4) + (sbase << 2) + holdoff);
        }

        // ---- main reduction: warp's 16 k4-chunks, 24 rows, lane = batch ----
        ull acc[24];
#pragma unroll
        for (int r = 0; r < 24; r++) acc[r] = 0ull;

        const ulonglong2* hp = ((const ulonglong2*)g_hp4) + sbase
                             + (size_t)(w * 16) * 32 + lane;

        ulonglong2 h0v = __ldcg(hp);
        ulonglong2 h1v = __ldcg(hp + 32);
#pragma unroll 4
        for (int kk = 0; kk < 16; kk++) {
            // depth-2 prefetch (overread lands inside g_hp4; unused)
            ulonglong2 h2v = __ldcg(hp + (size_t)(kk + 2) * 32);
            const float* wb = wb0 + kk * 4;
#pragma unroll
            for (int r = 0; r < 24; r++) {
                ulonglong2 wv = *(const ulonglong2*)(wb + r * 1024);
                FMA2(acc[r], wv.x, h0v.x);
                FMA2(acc[r], wv.y, h0v.y);
            }
            h0v = h1v; h1v = h2v;
        }

        // fold f32x2 and publish partials: sex[w][r][lane]
#pragma unroll
        for (int r = 0; r < 24; r++) {
            float lo, hi; UNPK(lo, hi, acc[r]);
            sex[(w * 24 + r) * 32 + lane] = lo + hi;
        }
        __syncthreads();

        // ---- epilogue: thread (u=w, b=lane), tid < 256 ----
        if (epi) {
            float hz = bz, hr = br, hq = bq;
#pragma unroll
            for (int w2 = 0; w2 < 16; w2++) {
                hz += sex[(w2 * 24 + w * 3 + 0) * 32 + lane];
                hr += sex[(w2 * 24 + w * 3 + 1) * 32 + lane];
                hq += sex[(w2 * 24 + w * 3 + 2) * 32 + lane];
            }
            float zg = __fdividef(1.f, 1.f + __expf(-(ez + hz)));
            float rg = __fdividef(1.f, 1.f + __expf(-(er + hr)));
            float xq = eq + rg * hq;
            float e2 = __expf(2.f * xq);
            float hc = 1.f - __fdividef(2.f, e2 + 1.f);
            float hn = zg * hold + (1.f - zg) * hc;

            __stcg(((float*)g_hp4) + ((sbase + 8192) << 2) + holdoff, hn); // packed
            __stcg(&g_hf[(size_t)s * 32768 + (size_t)lane * 1024 + j], hn); // flat
        }

        // ---- fence-free grid barrier (release arrive / acquire spin) ----
        __syncthreads();
        if (s < TSTEPS) {
            if (tid == 0) {
                asm volatile("red.release.gpu.global.add.u32 [%0], %1;"
                             :: "l"(&g_cnt[s]), "r"(1u) : "memory");
                unsigned v;
                do {
                    asm volatile("ld.acquire.gpu.global.u32 %0, [%1];"
                                 : "=r"(v) : "l"(&g_cnt[s]) : "memory");
                } while (v < (unsigned)NCTA);
            }
            __syncthreads();
        }
    }
}

// ---------------- launch ----------------
extern "C" void kernel_launch(void* const* d_in, const int* in_sizes, int n_in,
                              void* d_out, int out_size) {
    const int*   y   = (const int*)d_in[0];
    const float* emb = (const float*)d_in[1];
    const float* Wx  = (const float*)d_in[2];
    const float* Wh  = (const float*)d_in[3];
    const float* bx  = (const float*)d_in[4];
    const float* bh  = (const float*)d_in[5];
    const float* Wd  = (const float*)d_in[6];
    const float* bd  = (const float*)d_in[7];
    const float* h0  = (const float*)d_in[8];
    float* out = (float*)d_out;

    float *pE, *pHf;
    cudaGetSymbolAddress((void**)&pE, g_Eproj);
    cudaGetSymbolAddress((void**)&pHf, g_hf);

    cudaFuncSetAttribute(gru_persist_kernel,
                         cudaFuncAttributeMaxDynamicSharedMemorySize, STEP_SMEM);

    // init packed h0 + reset barrier counters (every replay)
    init_kernel<<<32, 1024>>>(h0);
    // WhT = transpose(Wh)
    transpose_wh_kernel<<<dim3(96, 32), dim3(32, 32)>>>(Wh);
    // Eproj = embed_table @ Wx + bx (only 1024 distinct token rows)
    gemm_bias_kernel<<<dim3(48, 16), 256>>>(emb, Wx, bx, pE, 1024, N3, 1024, 0);
    // persistent GRU recurrence (513 steps, one launch)
    gru_persist_kernel<<<NCTA, 512, STEP_SMEM>>>(bh, y);
    // outs[b,t,:] = h_{t+1}[b,:] @ Wd + bd
    gemm_bias_kernel<<<dim3(16, 257), 256>>>(pHf + 32768, Wd, bd, out,
                                             TSTEPS * BATCH, 1024, 1024, 1);
}